// round 8
// baseline (speedup 1.0000x reference)
#include <cuda_runtime.h>

#define ENC_LEVELS 80
#define NPAIRS     (ENC_LEVELS / 2)   // 40 float4 per position

// ---------------------------------------------------------------------------
// Compile-time tables. For v = m * 2^(Ev-150) (fp32 bits):
//   frac(v / 2pi) = frac(m * frac(2^(Ev-150) / 2pi))
// T[Ev] = frac(2^(Ev-150)/2pi) in 2^-64 fixed point, from the bits of 2/pi.
// ---------------------------------------------------------------------------
namespace petab {

constexpr unsigned int TP[12] = {   // fdlibm two_over_pi, 24-bit chunks
    0xA2F983, 0x6E4E44, 0x1529FC, 0x2757D1, 0xF534DD, 0xC0DB62,
    0x95993C, 0x439041, 0xFE5163, 0xABDEBB, 0xC561B7, 0x246E3A
};

constexpr int tp_bit(int i) {       // bit i (1-indexed) of frac(2/pi)
    if (i < 1 || i > 12 * 24) return 0;
    int c = (i - 1) / 24, b = (i - 1) % 24;
    return (int)((TP[c] >> (23 - b)) & 1u);
}

constexpr unsigned long long make_T(int ev) {
    int k = ev - 150;
    unsigned long long t = 0;
    for (int j = 0; j < 64; j++)
        t = (t << 1) | (unsigned long long)tp_bit(k - 1 + j);
    t += (unsigned long long)tp_bit(k + 63);   // round (mod-2^64 wrap ok)
    return t;
}

constexpr double pow125(int i) {
    double b = 1.25, s = 1.0;
    while (i) { if (i & 1) s *= b; b *= b; i >>= 1; }
    return s;
}

struct Tables {
    unsigned long long T[256];
    float S[ENC_LEVELS];
    constexpr Tables() : T(), S() {
        for (int e = 0; e < 256; e++) T[e] = make_T(e);
        for (int i = 0; i < ENC_LEVELS; i++)
            S[i] = (float)pow125(i) * 3.14159265358979323846f;  // * fl32(pi)
    }
};

} // namespace petab

__device__ constexpr petab::Tables g_tab = petab::Tables();

#define TWO_PI_F 6.28318530717958647692f

// (sin, cos) of v = fl32(pf*s) via exponent-table fixed-point reduction.
__device__ __forceinline__ float2 pe_pair(float pf, float s,
                                          const unsigned long long* __restrict__ sT) {
    float v = __fmul_rn(pf, s);
    unsigned int iv = __float_as_uint(v);
    unsigned long long T = sT[iv >> 23];                    // LDS.64
    unsigned int m   = (iv & 0x7FFFFFu) | 0x800000u;        // 24-bit mantissa
    unsigned int Tlo = (unsigned int)T;
    unsigned int Thi = (unsigned int)(T >> 32);
    unsigned int h = __umulhi(m, Tlo) + m * Thi + 0x80000000u;  // +0.5 turn center
    float uf = __uint_as_float(0x3F800000u | (h >> 9));     // 1 + frac'
    float theta = (uf - 1.5f) * TWO_PI_F;                   // [-pi, pi)
    float2 sc;
    sc.x = __sinf(theta);                                   // MUFU.SIN
    sc.y = __cosf(theta);                                   // MUFU.COS
    return sc;
}

__device__ __forceinline__ float4 pe_row(float pf, float s0, float s1,
                                         const unsigned long long* __restrict__ sT) {
    float2 a = pe_pair(pf, s0, sT);
    float2 b = pe_pair(pf, s1, sT);
    float4 r; r.x = a.x; r.y = a.y; r.z = b.x; r.w = b.y;
    return r;
}

// Flat q-striding with total-threads % 40 == 0: under q = gtid + k*Total,
// x = gtid%40 and the scales are PER-THREAD CONSTANTS (one div at entry),
// p advances by pstep = Total/40 per quad-step. Stores stay warp-contiguous.
// 4 quad-steps per iteration: 4 independent chains, 4 batched STG.128.
__global__ void __launch_bounds__(256, 8)
pe_main_kernel(float4* __restrict__ out, int n, int pstep) {
    __shared__ unsigned long long sT[256];
    int t = threadIdx.x;
    sT[t] = g_tab.T[t];
    __syncthreads();

    int gtid = blockIdx.x * 256 + t;
    int p = gtid / 40;                        // once per thread
    int x = gtid - p * 40;
    float s0 = g_tab.S[2 * x];
    float s1 = g_tab.S[2 * x + 1];

    float pf  = (float)p;                     // exact: p < 2^24 always
    float pfs = (float)pstep;                 // exact integer float
    float4* op = out + gtid;
    size_t  os = (size_t)pstep * NPAIRS;      // == total threads

    int fast_lim = n - 3 * pstep;             // all 4 rows valid below this
    while (p < fast_lim) {
        float4 r0 = pe_row(pf,              s0, s1, sT);
        float4 r1 = pe_row(pf + pfs,        s0, s1, sT);
        float4 r2 = pe_row(pf + 2.0f * pfs, s0, s1, sT);
        float4 r3 = pe_row(pf + 3.0f * pfs, s0, s1, sT);
        op[0]      = r0;
        op[os]     = r1;
        op[2 * os] = r2;
        op[3 * os] = r3;
        p  += 4 * pstep;
        pf += 4.0f * pfs;
        op += 4 * os;
    }
    while (p < n) {                           // tail: at most 3 rows
        *op = pe_row(pf, s0, s1, sT);
        p  += pstep;
        pf += pfs;
        op += os;
    }
}

extern "C" void kernel_launch(void* const* d_in, const int* in_sizes, int n_in,
                              void* d_out, int out_size) {
    (void)d_in; (void)n_in; (void)out_size;   // reference ignores pos values
    int n = in_sizes[0];

    // grid must be a multiple of 5 so total threads (grid*256) % 40 == 0.
    int blocks = 1180;                         // ~7.97 blocks/SM, 64 warps resident
    long long max_needed = ((long long)n * NPAIRS + 255) / 256;
    if ((long long)blocks > max_needed) {
        blocks = (int)((max_needed + 4) / 5 * 5);   // round up to multiple of 5
        if (blocks < 5) blocks = 5;
    }
    int pstep = blocks * 256 / NPAIRS;         // positions advanced per quad-step
    pe_main_kernel<<<blocks, 256>>>((float4*)d_out, n, pstep);
}

// round 9
// speedup vs baseline: 1.0298x; 1.0298x over previous
#include <cuda_runtime.h>

#define ENC_LEVELS 80
#define NPAIRS     (ENC_LEVELS / 2)   // 40 float4 per position
#define CHUNK_QUADS 1024              // 16 KB staged per bulk store
#define CHUNK_BYTES (CHUNK_QUADS * 16)

// ---------------------------------------------------------------------------
// Compile-time tables. For v = m * 2^(Ev-150) (fp32 bits):
//   frac(v / 2pi) = frac(m * frac(2^(Ev-150) / 2pi))
// T[Ev] = frac(2^(Ev-150)/2pi) in 2^-64 fixed point, from the bits of 2/pi.
// ---------------------------------------------------------------------------
namespace petab {

constexpr unsigned int TP[12] = {   // fdlibm two_over_pi, 24-bit chunks
    0xA2F983, 0x6E4E44, 0x1529FC, 0x2757D1, 0xF534DD, 0xC0DB62,
    0x95993C, 0x439041, 0xFE5163, 0xABDEBB, 0xC561B7, 0x246E3A
};

constexpr int tp_bit(int i) {       // bit i (1-indexed) of frac(2/pi)
    if (i < 1 || i > 12 * 24) return 0;
    int c = (i - 1) / 24, b = (i - 1) % 24;
    return (int)((TP[c] >> (23 - b)) & 1u);
}

constexpr unsigned long long make_T(int ev) {
    int k = ev - 150;
    unsigned long long t = 0;
    for (int j = 0; j < 64; j++)
        t = (t << 1) | (unsigned long long)tp_bit(k - 1 + j);
    t += (unsigned long long)tp_bit(k + 63);   // round (mod-2^64 wrap ok)
    return t;
}

constexpr double pow125(int i) {
    double b = 1.25, s = 1.0;
    while (i) { if (i & 1) s *= b; b *= b; i >>= 1; }
    return s;
}

struct Tables {
    unsigned long long T[256];
    float S[ENC_LEVELS];
    constexpr Tables() : T(), S() {
        for (int e = 0; e < 256; e++) T[e] = make_T(e);
        for (int i = 0; i < ENC_LEVELS; i++)
            S[i] = (float)pow125(i) * 3.14159265358979323846f;  // * fl32(pi)
    }
};

} // namespace petab

__device__ constexpr petab::Tables g_tab = petab::Tables();

#define TWO_PI_F 6.28318530717958647692f

// (sin, cos) of v = fl32(pf*s) via exponent-table fixed-point reduction.
__device__ __forceinline__ float2 pe_pair(float pf, float s,
                                          const unsigned long long* __restrict__ sT) {
    float v = __fmul_rn(pf, s);
    unsigned int iv = __float_as_uint(v);
    unsigned long long T = sT[iv >> 23];                    // LDS.64
    unsigned int m   = (iv & 0x7FFFFFu) | 0x800000u;        // 24-bit mantissa
    unsigned int Tlo = (unsigned int)T;
    unsigned int Thi = (unsigned int)(T >> 32);
    unsigned int h = __umulhi(m, Tlo) + m * Thi + 0x80000000u;  // +0.5 turn center
    float uf = __uint_as_float(0x3F800000u | (h >> 9));     // 1 + frac'
    float theta = (uf - 1.5f) * TWO_PI_F;                   // [-pi, pi)
    float2 sc;
    sc.x = __sinf(theta);                                   // MUFU.SIN
    sc.y = __cosf(theta);                                   // MUFU.COS
    return sc;
}

// One quad (float4) = levels (2x, 2x+1) of position p, where q = p*40 + x.
__device__ __forceinline__ float4 pe_quad(unsigned int q,
                                          const unsigned long long* __restrict__ sT,
                                          const float2* __restrict__ sS) {
    unsigned int p = q / 40u;            // UMULHI magic
    unsigned int x = q - p * 40u;
    float pf = (float)p;                 // exact: p < 2^24
    float2 s = sS[x];                    // LDS.64
    float2 a = pe_pair(pf, s.x, sT);
    float2 b = pe_pair(pf, s.y, sT);
    float4 r; r.x = a.x; r.y = a.y; r.z = b.x; r.w = b.y;
    return r;
}

__device__ __forceinline__ unsigned int smem_u32(const void* p) {
    return (unsigned int)__cvta_generic_to_shared(p);
}

// Staged-write kernel: compute a 16KB tile into SMEM, then one elected
// cp.async.bulk (TMA/UBLKCP) shared->global moves it — bypassing the
// per-thread STG / L1TEX-wavefront store path entirely. Double-buffered.
__global__ void __launch_bounds__(256)
pe_main_kernel(float4* __restrict__ out, unsigned int nq) {
    __shared__ __align__(16) float4 buf[2][CHUNK_QUADS];    // 2 x 16 KB
    __shared__ unsigned long long sT[256];
    __shared__ float2 sS[NPAIRS];

    int t = threadIdx.x;
    sT[t] = g_tab.T[t];
    if (t < NPAIRS) sS[t] = make_float2(g_tab.S[2 * t], g_tab.S[2 * t + 1]);
    __syncthreads();

    unsigned int nchunks = (nq + CHUNK_QUADS - 1) / CHUNK_QUADS;
    unsigned int chunk   = blockIdx.x;
    unsigned int cstride = gridDim.x;

    int buf_id = 0, iter = 0;
    for (; chunk < nchunks; chunk += cstride, buf_id ^= 1, iter++) {
        // Gate buffer reuse: store issued 2 iterations ago (same buffer) done.
        if (iter >= 2) {
            if (t == 0) asm volatile("cp.async.bulk.wait_group 1;" ::: "memory");
        }
        if (iter >= 1) __syncthreads();   // all threads see buffer free / data fence

        unsigned int qbase = chunk * CHUNK_QUADS;
        unsigned int q0 = qbase + (unsigned int)t;
        float4* bb = &buf[buf_id][0];

        if (qbase + CHUNK_QUADS <= nq) {  // full chunk (overwhelmingly common)
            float4 r0 = pe_quad(q0,        sT, sS);
            float4 r1 = pe_quad(q0 + 256u, sT, sS);
            float4 r2 = pe_quad(q0 + 512u, sT, sS);
            float4 r3 = pe_quad(q0 + 768u, sT, sS);
            bb[t]       = r0;
            bb[t + 256] = r1;
            bb[t + 512] = r2;
            bb[t + 768] = r3;
        } else {                          // tail chunk
            #pragma unroll
            for (int j = 0; j < 4; j++) {
                unsigned int q = q0 + (unsigned int)(j * 256);
                if (q < nq) bb[t + j * 256] = pe_quad(q, sT, sS);
            }
        }
        __syncthreads();                  // tile complete

        if (t == 0) {
            unsigned int valid = nq - qbase;
            if (valid > CHUNK_QUADS) valid = CHUNK_QUADS;
            unsigned int bytes = valid * 16u;
            asm volatile("fence.proxy.async.shared::cta;" ::: "memory");
            asm volatile(
                "cp.async.bulk.global.shared::cta.bulk_group [%0], [%1], %2;"
                :: "l"(out + qbase), "r"(smem_u32(bb)), "r"(bytes)
                : "memory");
            asm volatile("cp.async.bulk.commit_group;" ::: "memory");
        }
    }
    if (t == 0) asm volatile("cp.async.bulk.wait_group 0;" ::: "memory");
}

extern "C" void kernel_launch(void* const* d_in, const int* in_sizes, int n_in,
                              void* d_out, int out_size) {
    (void)d_in; (void)n_in; (void)out_size;  // reference ignores pos values
    unsigned int n  = (unsigned int)in_sizes[0];
    unsigned int nq = n * (unsigned int)NPAIRS;     // total float4 quads

    int blocks = 148 * 6;                    // 34KB smem/block -> 6 blocks/SM
    unsigned int nchunks = (nq + CHUNK_QUADS - 1) / CHUNK_QUADS;
    if ((unsigned int)blocks > nchunks) blocks = (int)nchunks;
    if (blocks < 1) blocks = 1;
    pe_main_kernel<<<blocks, 256>>>((float4*)d_out, nq);
}